// round 6
// baseline (speedup 1.0000x reference)
#include <cuda_runtime.h>
#include <cuda_bf16.h>
#include <math.h>
#include <stdint.h>

#define BB 2
#define HH 480
#define WW 640
#define DD 256
#define HC 60
#define WC 80
#define NN 4800          // HC*WC
#define TOTAL_PIX (BB*HH*WW)

// ---------------- device scratch ----------------
// acc: 0 pos1, 1 neg1, 2 npos1, 3 pos2, 4 neg2, 5 npos2, 6 normalization, 7 desc_sum
__device__ double g_acc[8];   // static zero-init; finalize re-zeros after each use
__device__ __align__(16) __nv_bfloat16 g_dnorm[BB*NN*DD];   // (b, ij, d) bf16 normalized
__device__ __align__(16) __nv_bfloat16 g_wdnorm[BB*NN*DD];
__device__ float4 g_rowgeo[BB*NN];   // {wy, wx, vm_c, 0}
__device__ float4 g_colgeo[BB*NN];   // {cy, cx, wvm_c, 0}

// ---------------- helpers ----------------
__device__ __forceinline__ float warpsum(float v) {
    #pragma unroll
    for (int o = 16; o; o >>= 1) v += __shfl_down_sync(0xffffffffu, v, o);
    return v;
}

__device__ __forceinline__ uint32_t smem_u32(const void* p) {
    uint32_t a;
    asm("{ .reg .u64 t; cvta.to.shared.u64 t, %1; cvt.u32.u64 %0, t; }" : "=r"(a) : "l"(p));
    return a;
}

__device__ __forceinline__ void cp_async16(uint32_t dst, const void* src, uint32_t bytes) {
    asm volatile("cp.async.cg.shared.global [%0], [%1], 16, %2;"
                 :: "r"(dst), "l"(src), "r"(bytes) : "memory");
}
#define CP_COMMIT() asm volatile("cp.async.commit_group;" ::: "memory")
#define CP_WAIT(n)  asm volatile("cp.async.wait_group %0;" :: "n"(n) : "memory")

// ---------------- detector losses + normalization sum (float4) ----------------
__global__ void detector_kernel(const float4* __restrict__ prob,
                                const float4* __restrict__ ht,
                                const float4* __restrict__ vm,
                                const float4* __restrict__ wprob,
                                const float4* __restrict__ wht,
                                const float4* __restrict__ wvm) {
    float vals[7] = {0, 0, 0, 0, 0, 0, 0};
    const int n4 = TOTAL_PIX / 4;
    for (int i = blockIdx.x * blockDim.x + threadIdx.x; i < n4;
         i += gridDim.x * blockDim.x) {
        float4 p4 = prob[i], h4 = ht[i], v4 = vm[i];
        float4 wp4 = wprob[i], wh4 = wht[i], wv4 = wvm[i];
        #pragma unroll
        for (int q = 0; q < 4; q++) {
            float p = ((const float*)&p4)[q], h = ((const float*)&h4)[q], v = ((const float*)&v4)[q];
            float pi = (h == 1.0f) ? 1.f : 0.f;
            float ni = (h < 1.0f) ? 1.f : 0.f;
            float nw = (1.f - h) * (1.f - h); nw *= nw;
            vals[0] += logf(p + 1e-7f) * (1.f - p) * (1.f - p) * pi * v;
            vals[1] += logf(1.f - p + 1e-7f) * p * p * nw * ni * v;
            vals[2] += pi;
            float wp = ((const float*)&wp4)[q], wh = ((const float*)&wh4)[q], wv = ((const float*)&wv4)[q];
            float wpi = (wh == 1.0f) ? 1.f : 0.f;
            float wni = (wh < 1.0f) ? 1.f : 0.f;
            float wnw = (1.f - wh) * (1.f - wh); wnw *= wnw;
            vals[3] += logf(wp + 1e-7f) * (1.f - wp) * (1.f - wp) * wpi * wv;
            vals[4] += logf(1.f - wp + 1e-7f) * wp * wp * wnw * wni * wv;
            vals[5] += wpi;
            vals[6] += wv;
        }
    }
    __shared__ float w[8];
    int lane = threadIdx.x & 31, warp = threadIdx.x >> 5;
    for (int q = 0; q < 7; q++) {
        float v = warpsum(vals[q]);
        if (lane == 0) w[warp] = v;
        __syncthreads();
        if (threadIdx.x == 0) {
            float s = 0;
            for (int u = 0; u < (int)(blockDim.x >> 5); u++) s += w[u];
            atomicAdd(&g_acc[q], (double)s);
        }
        __syncthreads();
    }
}

// ---------------- descriptor normalize + transpose (fp32 -> bf16), both tensors ----------------
__global__ void normdesc_kernel(const float* __restrict__ src0, __nv_bfloat16* __restrict__ dst0,
                                const float* __restrict__ src1, __nv_bfloat16* __restrict__ dst1) {
    __shared__ float tile[DD][33];
    __shared__ float part[16][32];
    __shared__ float inv[32];
    int which = blockIdx.x >= BB * (NN / 32);
    int blk = blockIdx.x - which * BB * (NN / 32);
    const float* src = which ? src1 : src0;
    __nv_bfloat16* dst = which ? dst1 : dst0;
    int b = blk / (NN / 32);
    int jt = blk % (NN / 32);
    int base = jt * 32;
    const float* s = src + (size_t)b * DD * NN;
    for (int idx = threadIdx.x; idx < DD * 32; idx += 512) {
        int d = idx >> 5, j = idx & 31;
        tile[d][j] = s[d * NN + base + j];
    }
    __syncthreads();
    {
        int j = threadIdx.x & 31, g = threadIdx.x >> 5;
        float acc = 0;
        for (int d = g; d < DD; d += 16) { float v = tile[d][j]; acc += v * v; }
        part[g][j] = acc;
    }
    __syncthreads();
    if (threadIdx.x < 32) {
        float s2 = 0;
        #pragma unroll
        for (int g2 = 0; g2 < 16; g2++) s2 += part[g2][threadIdx.x];
        inv[threadIdx.x] = 1.0f / fmaxf(sqrtf(s2), 1e-12f);
    }
    __syncthreads();
    __nv_bfloat16* o = dst + (size_t)b * NN * DD;
    for (int idx = threadIdx.x; idx < 32 * DD; idx += 512) {
        int jj = idx >> 8, d = idx & 255;
        o[(size_t)(base + jj) * DD + d] = __float2bfloat16(tile[d][jj] * inv[jj]);
    }
}

// ---------------- warped coords + downsampled masks ----------------
__device__ __forceinline__ float bilinear_ds(const float* __restrict__ img, int i, int j) {
    float sr = (i + 0.5f) * ((float)HH / HC) - 0.5f;
    sr = fminf(fmaxf(sr, 0.f), (float)(HH - 1));
    int r0 = (int)floorf(sr); int r1 = min(r0 + 1, HH - 1); float wr = sr - (float)r0;
    float sc = (j + 0.5f) * ((float)WW / WC) - 0.5f;
    sc = fminf(fmaxf(sc, 0.f), (float)(WW - 1));
    int c0 = (int)floorf(sc); int c1 = min(c0 + 1, WW - 1); float wc = sc - (float)c0;
    float a = img[r0 * WW + c0] * (1.f - wr) + img[r1 * WW + c0] * wr;
    float b = img[r0 * WW + c1] * (1.f - wr) + img[r1 * WW + c1] * wr;
    return a * (1.f - wc) + b * wc;
}

__global__ void coords_kernel(const float* __restrict__ vm,
                              const float* __restrict__ wvm,
                              const float* __restrict__ Hm) {
    int idx = blockIdx.x * blockDim.x + threadIdx.x;
    if (idx >= BB * NN) return;
    int b = idx / NN, ij = idx % NN;
    int i = ij / WC, j = ij % WC;
    float y = (float)(i * 8 + 4), x = (float)(j * 8 + 4);
    const float* Hb = Hm + b * 9;
    float w0 = Hb[0] * x + Hb[1] * y + Hb[2];
    float w1 = Hb[3] * x + Hb[4] * y + Hb[5];
    float w2 = Hb[6] * x + Hb[7] * y + Hb[8];
    float vmc  = (bilinear_ds(vm  + (size_t)b * HH * WW, i, j) > 0.5f) ? 1.f : 0.f;
    float wvmc = (bilinear_ds(wvm + (size_t)b * HH * WW, i, j) > 0.5f) ? 1.f : 0.f;
    g_rowgeo[idx] = make_float4(w1 / w2, w0 / w2, vmc, 0.f);
    g_colgeo[idx] = make_float4(y, x, wvmc, 0.f);
}

// ---------------- main: bf16 mma.sync GEMM, KC=64, 1 barrier/chunk ----------------
#define TILE 128
#define KC 64
#define KSTR 72                       // halfs/row: 128B data + 16B pad; conflict-free ldmatrix
#define MAT_BYTES (TILE * KSTR * 2)   // 18432
#define STAGE_BYTES (2 * MAT_BYTES)   // A then B per stage
#define ROW_OFF (2 * STAGE_BYTES)     // 73728
#define COL_OFF (ROW_OFF + TILE * 16)
#define WRED_OFF (COL_OFF + TILE * 16)
#define SMEM_TOTAL (WRED_OFF + 64)
#define NCHUNK (DD / KC)              // 4

__device__ __forceinline__ float lossterm(float acc, float4 r, float4 c) {
    float dot = fmaxf(acc, 0.f);
    float pd = fmaxf(1.0f - dot, 0.f);
    float nd = fmaxf(dot - 0.2f, 0.f);
    float dy = c.x - r.x, dx = c.y - r.y;
    float d2 = dy * dy + dx * dx;
    float w = r.z * c.z;
    return (d2 <= 56.25f) ? 250.f * pd * w : nd * w;   // (CELL-0.5)^2 = 56.25
}

__global__ __launch_bounds__(256, 2) void gemm_loss_kernel() {
    extern __shared__ __align__(16) char dsm[];
    float4* s_row = (float4*)(dsm + ROW_OFF);
    float4* s_col = (float4*)(dsm + COL_OFF);
    float*  wred  = (float*)(dsm + WRED_OFF);

    int b = blockIdx.z;
    int i0 = blockIdx.y * TILE;
    int j0 = blockIdx.x * TILE;
    int tid = threadIdx.x;
    int wid = tid >> 5, lane = tid & 31;

    if (tid < TILE) {
        int r = i0 + tid;
        s_row[tid] = (r < NN) ? g_rowgeo[b * NN + r] : make_float4(0.f, 0.f, 0.f, 0.f);
    } else {
        int t = tid - TILE;
        int c = j0 + t;
        s_col[t] = (c < NN) ? g_colgeo[b * NN + c] : make_float4(0.f, 0.f, 0.f, 0.f);
    }

    const char* A  = (const char*)(g_dnorm  + (size_t)b * NN * DD);
    const char* Bm = (const char*)(g_wdnorm + (size_t)b * NN * DD);

    // cp.async geometry: each chunk row = 128B = 8 x 16B; thread t handles
    // row t>>1, 64B half (t&1) of both A and B (4 segs each).
    int rowT = tid >> 1, colb = (tid & 1) * 64;
    uint32_t okA = (i0 + rowT < NN) ? 16u : 0u;
    uint32_t okB = (j0 + rowT < NN) ? 16u : 0u;
    const char* gA = A  + (size_t)(i0 + rowT) * (DD * 2) + colb;
    const char* gB = Bm + (size_t)(j0 + rowT) * (DD * 2) + colb;
    uint32_t smem0 = smem_u32(dsm);
    uint32_t sA = smem0 + rowT * (KSTR * 2) + colb;
    uint32_t sB = sA + (uint32_t)MAT_BYTES;

    int m_base = (wid >> 2) * 64;     // 0 or 64
    int n_base = (wid & 3) * 32;      // 0,32,64,96
    int g = lane >> 3, lr = lane & 7;

    float c[4][4][4];
    #pragma unroll
    for (int i = 0; i < 4; i++)
        #pragma unroll
        for (int j = 0; j < 4; j++)
            #pragma unroll
            for (int q = 0; q < 4; q++) c[i][j][q] = 0.f;

    // ldmatrix lane offsets (bytes)
    uint32_t a_row_off = (uint32_t)((m_base + (g & 1) * 8 + lr) * KSTR + (g >> 1) * 8) * 2;
    uint32_t b_row_off = (uint32_t)((n_base + (g >> 1) * 8 + lr) * KSTR + (g & 1) * 8) * 2;

    // prologue: chunk 0 -> stage 0
    #pragma unroll
    for (int q = 0; q < 4; q++) {
        cp_async16(sA + q * 16, gA + q * 16, okA);
        cp_async16(sB + q * 16, gB + q * 16, okB);
    }
    CP_COMMIT();

    #pragma unroll
    for (int ck = 0; ck < NCHUNK; ck++) {
        int s = ck & 1;
        CP_WAIT(0);          // chunk ck's copy complete
        __syncthreads();     // stage s readable; all reads of stage 1-s finished
        if (ck + 1 < NCHUNK) {
            uint32_t so = (uint32_t)((ck + 1) & 1) * STAGE_BYTES;
            int go = (ck + 1) * (KC * 2);
            #pragma unroll
            for (int q = 0; q < 4; q++) {
                cp_async16(sA + so + q * 16, gA + go + q * 16, okA);
                cp_async16(sB + so + q * 16, gB + go + q * 16, okB);
            }
            CP_COMMIT();
        }

        uint32_t abase = smem0 + s * (uint32_t)STAGE_BYTES + a_row_off;
        uint32_t bbase = smem0 + s * (uint32_t)STAGE_BYTES + (uint32_t)MAT_BYTES + b_row_off;
        #pragma unroll
        for (int ks = 0; ks < KC; ks += 16) {
            uint32_t af[4][4];
            #pragma unroll
            for (int mt = 0; mt < 4; mt++) {
                uint32_t addr = abase + (uint32_t)(mt * 16 * KSTR + ks) * 2;
                asm volatile("ldmatrix.sync.aligned.m8n8.x4.shared.b16 {%0,%1,%2,%3}, [%4];"
                             : "=r"(af[mt][0]), "=r"(af[mt][1]), "=r"(af[mt][2]), "=r"(af[mt][3])
                             : "r"(addr));
            }
            #pragma unroll
            for (int np = 0; np < 2; np++) {
                uint32_t bf[4];
                uint32_t addr = bbase + (uint32_t)(np * 16 * KSTR + ks) * 2;
                asm volatile("ldmatrix.sync.aligned.m8n8.x4.shared.b16 {%0,%1,%2,%3}, [%4];"
                             : "=r"(bf[0]), "=r"(bf[1]), "=r"(bf[2]), "=r"(bf[3])
                             : "r"(addr));
                #pragma unroll
                for (int h = 0; h < 2; h++) {
                    int nt = np * 2 + h;
                    #pragma unroll
                    for (int mt = 0; mt < 4; mt++) {
                        asm volatile(
                            "mma.sync.aligned.m16n8k16.row.col.f32.bf16.bf16.f32 "
                            "{%0,%1,%2,%3}, {%4,%5,%6,%7}, {%8,%9}, {%0,%1,%2,%3};"
                            : "+f"(c[mt][nt][0]), "+f"(c[mt][nt][1]),
                              "+f"(c[mt][nt][2]), "+f"(c[mt][nt][3])
                            : "r"(af[mt][0]), "r"(af[mt][1]), "r"(af[mt][2]), "r"(af[mt][3]),
                              "r"(bf[h * 2]), "r"(bf[h * 2 + 1]));
                    }
                }
            }
        }
    }

    // fused epilogue
    int qr = lane >> 2, qc = (lane & 3) * 2;
    float lsum = 0.f;
    #pragma unroll
    for (int mt = 0; mt < 4; mt++) {
        float4 r0 = s_row[m_base + mt * 16 + qr];
        float4 r1 = s_row[m_base + mt * 16 + qr + 8];
        #pragma unroll
        for (int nt = 0; nt < 4; nt++) {
            float4 c0 = s_col[n_base + nt * 8 + qc];
            float4 c1 = s_col[n_base + nt * 8 + qc + 1];
            lsum += lossterm(c[mt][nt][0], r0, c0);
            lsum += lossterm(c[mt][nt][1], r0, c1);
            lsum += lossterm(c[mt][nt][2], r1, c0);
            lsum += lossterm(c[mt][nt][3], r1, c1);
        }
    }

    float v = warpsum(lsum);
    __syncthreads();               // compute done everywhere before wred reuse
    if (lane == 0) wred[wid] = v;
    __syncthreads();
    if (tid == 0) {
        float s = 0;
        #pragma unroll
        for (int u = 0; u < 8; u++) s += wred[u];
        atomicAdd(&g_acc[7], (double)s);
    }
}

// ---------------- finalize (also re-zeros accumulators for next replay) ----------------
__global__ void finalize_kernel(float* __restrict__ out) {
    double np1 = g_acc[2];
    double pl  = (np1 == 0.0) ? -g_acc[1] : -(g_acc[0] + g_acc[1]) / fmax(np1, 1.0);
    double np2 = g_acc[5];
    double wpl = (np2 == 0.0) ? -g_acc[4] : -(g_acc[3] + g_acc[4]) / fmax(np2, 1.0);
    double dl  = g_acc[7] / g_acc[6];
    out[0] = (float)(pl + wpl + 1e-4 * dl);
    out[1] = (float)pl;
    out[2] = (float)wpl;
    out[3] = (float)dl;
    #pragma unroll
    for (int q = 0; q < 8; q++) g_acc[q] = 0.0;
}

// ---------------- launch ----------------
extern "C" void kernel_launch(void* const* d_in, const int* in_sizes, int n_in,
                              void* d_out, int out_size) {
    const float* prob  = (const float*)d_in[0];
    const float* ht    = (const float*)d_in[1];
    const float* vm    = (const float*)d_in[2];
    const float* wprob = (const float*)d_in[3];
    const float* wht   = (const float*)d_in[4];
    const float* wvm   = (const float*)d_in[5];
    const float* desc  = (const float*)d_in[6];
    const float* wdesc = (const float*)d_in[7];
    const float* Hm    = (const float*)d_in[8];
    float* out = (float*)d_out;

    cudaFuncSetAttribute(gemm_loss_kernel,
                         cudaFuncAttributeMaxDynamicSharedMemorySize, SMEM_TOTAL);

    detector_kernel<<<600, 256>>>((const float4*)prob, (const float4*)ht, (const float4*)vm,
                                  (const float4*)wprob, (const float4*)wht, (const float4*)wvm);

    __nv_bfloat16* dnorm;  cudaGetSymbolAddress((void**)&dnorm,  g_dnorm);
    __nv_bfloat16* wdnorm; cudaGetSymbolAddress((void**)&wdnorm, g_wdnorm);
    normdesc_kernel<<<2 * BB * (NN / 32), 512>>>(desc, dnorm, wdesc, wdnorm);

    coords_kernel<<<(BB * NN + 255) / 256, 256>>>(vm, wvm, Hm);

    dim3 grid((NN + TILE - 1) / TILE, (NN + TILE - 1) / TILE, BB);
    gemm_loss_kernel<<<grid, 256, SMEM_TOTAL>>>();

    finalize_kernel<<<1, 1>>>(out);
}

// round 8
// speedup vs baseline: 1.0305x; 1.0305x over previous
#include <cuda_runtime.h>
#include <cuda_fp16.h>
#include <math.h>
#include <stdint.h>

#define BB 2
#define HH 480
#define WW 640
#define DD 256
#define HC 60
#define WC 80
#define NN 4800          // HC*WC
#define TOTAL_PIX (BB*HH*WW)

// ---------------- device scratch ----------------
// acc: 0 pos1, 1 neg1, 2 npos1, 3 pos2, 4 neg2, 5 npos2, 6 normalization, 7 desc_sum
__device__ double g_acc[8];   // static zero-init; finalize re-zeros after each use
__device__ __align__(16) __half g_dnorm[BB*NN*DD];   // (b, ij, d) fp16 normalized
__device__ __align__(16) __half g_wdnorm[BB*NN*DD];
__device__ float4 g_rowgeo[BB*NN];   // {wy, wx, vm_c, 0}
__device__ float4 g_colgeo[BB*NN];   // {cy, cx, wvm_c, 0}

// ---------------- helpers ----------------
__device__ __forceinline__ float warpsum(float v) {
    #pragma unroll
    for (int o = 16; o; o >>= 1) v += __shfl_down_sync(0xffffffffu, v, o);
    return v;
}

__device__ __forceinline__ uint32_t smem_u32(const void* p) {
    uint32_t a;
    asm("{ .reg .u64 t; cvta.to.shared.u64 t, %1; cvt.u32.u64 %0, t; }" : "=r"(a) : "l"(p));
    return a;
}

__device__ __forceinline__ void cp_async16(uint32_t dst, const void* src, uint32_t bytes) {
    asm volatile("cp.async.cg.shared.global [%0], [%1], 16, %2;"
                 :: "r"(dst), "l"(src), "r"(bytes) : "memory");
}
#define CP_COMMIT() asm volatile("cp.async.commit_group;" ::: "memory")
#define CP_WAIT(n)  asm volatile("cp.async.wait_group %0;" :: "n"(n) : "memory")

// ---------------- detector losses + normalization sum (float4) ----------------
__global__ void detector_kernel(const float4* __restrict__ prob,
                                const float4* __restrict__ ht,
                                const float4* __restrict__ vm,
                                const float4* __restrict__ wprob,
                                const float4* __restrict__ wht,
                                const float4* __restrict__ wvm) {
    float vals[7] = {0, 0, 0, 0, 0, 0, 0};
    const int n4 = TOTAL_PIX / 4;
    for (int i = blockIdx.x * blockDim.x + threadIdx.x; i < n4;
         i += gridDim.x * blockDim.x) {
        float4 p4 = prob[i], h4 = ht[i], v4 = vm[i];
        float4 wp4 = wprob[i], wh4 = wht[i], wv4 = wvm[i];
        #pragma unroll
        for (int q = 0; q < 4; q++) {
            float p = ((const float*)&p4)[q], h = ((const float*)&h4)[q], v = ((const float*)&v4)[q];
            float pi = (h == 1.0f) ? 1.f : 0.f;
            float ni = (h < 1.0f) ? 1.f : 0.f;
            float nw = (1.f - h) * (1.f - h); nw *= nw;
            vals[0] += logf(p + 1e-7f) * (1.f - p) * (1.f - p) * pi * v;
            vals[1] += logf(1.f - p + 1e-7f) * p * p * nw * ni * v;
            vals[2] += pi;
            float wp = ((const float*)&wp4)[q], wh = ((const float*)&wh4)[q], wv = ((const float*)&wv4)[q];
            float wpi = (wh == 1.0f) ? 1.f : 0.f;
            float wni = (wh < 1.0f) ? 1.f : 0.f;
            float wnw = (1.f - wh) * (1.f - wh); wnw *= wnw;
            vals[3] += logf(wp + 1e-7f) * (1.f - wp) * (1.f - wp) * wpi * wv;
            vals[4] += logf(1.f - wp + 1e-7f) * wp * wp * wnw * wni * wv;
            vals[5] += wpi;
            vals[6] += wv;
        }
    }
    __shared__ float w[8];
    int lane = threadIdx.x & 31, warp = threadIdx.x >> 5;
    for (int q = 0; q < 7; q++) {
        float v = warpsum(vals[q]);
        if (lane == 0) w[warp] = v;
        __syncthreads();
        if (threadIdx.x == 0) {
            float s = 0;
            for (int u = 0; u < (int)(blockDim.x >> 5); u++) s += w[u];
            atomicAdd(&g_acc[q], (double)s);
        }
        __syncthreads();
    }
}

// ---------------- descriptor normalize + transpose (fp32 -> fp16), both tensors ----------------
__global__ void normdesc_kernel(const float* __restrict__ src0, __half* __restrict__ dst0,
                                const float* __restrict__ src1, __half* __restrict__ dst1) {
    __shared__ float tile[DD][33];
    __shared__ float part[16][32];
    __shared__ float inv[32];
    int which = blockIdx.x >= BB * (NN / 32);
    int blk = blockIdx.x - which * BB * (NN / 32);
    const float* src = which ? src1 : src0;
    __half* dst = which ? dst1 : dst0;
    int b = blk / (NN / 32);
    int jt = blk % (NN / 32);
    int base = jt * 32;
    const float* s = src + (size_t)b * DD * NN;
    for (int idx = threadIdx.x; idx < DD * 32; idx += 512) {
        int d = idx >> 5, j = idx & 31;
        tile[d][j] = s[d * NN + base + j];
    }
    __syncthreads();
    {
        int j = threadIdx.x & 31, g = threadIdx.x >> 5;
        float acc = 0;
        for (int d = g; d < DD; d += 16) { float v = tile[d][j]; acc += v * v; }
        part[g][j] = acc;
    }
    __syncthreads();
    if (threadIdx.x < 32) {
        float s2 = 0;
        #pragma unroll
        for (int g2 = 0; g2 < 16; g2++) s2 += part[g2][threadIdx.x];
        inv[threadIdx.x] = 1.0f / fmaxf(sqrtf(s2), 1e-12f);
    }
    __syncthreads();
    __half* o = dst + (size_t)b * NN * DD;
    for (int idx = threadIdx.x; idx < 32 * DD; idx += 512) {
        int jj = idx >> 8, d = idx & 255;
        o[(size_t)(base + jj) * DD + d] = __float2half_rn(tile[d][jj] * inv[jj]);
    }
}

// ---------------- warped coords + downsampled masks ----------------
__device__ __forceinline__ float bilinear_ds(const float* __restrict__ img, int i, int j) {
    float sr = (i + 0.5f) * ((float)HH / HC) - 0.5f;
    sr = fminf(fmaxf(sr, 0.f), (float)(HH - 1));
    int r0 = (int)floorf(sr); int r1 = min(r0 + 1, HH - 1); float wr = sr - (float)r0;
    float sc = (j + 0.5f) * ((float)WW / WC) - 0.5f;
    sc = fminf(fmaxf(sc, 0.f), (float)(WW - 1));
    int c0 = (int)floorf(sc); int c1 = min(c0 + 1, WW - 1); float wc = sc - (float)c0;
    float a = img[r0 * WW + c0] * (1.f - wr) + img[r1 * WW + c0] * wr;
    float b = img[r0 * WW + c1] * (1.f - wr) + img[r1 * WW + c1] * wr;
    return a * (1.f - wc) + b * wc;
}

__global__ void coords_kernel(const float* __restrict__ vm,
                              const float* __restrict__ wvm,
                              const float* __restrict__ Hm) {
    int idx = blockIdx.x * blockDim.x + threadIdx.x;
    if (idx >= BB * NN) return;
    int b = idx / NN, ij = idx % NN;
    int i = ij / WC, j = ij % WC;
    float y = (float)(i * 8 + 4), x = (float)(j * 8 + 4);
    const float* Hb = Hm + b * 9;
    float w0 = Hb[0] * x + Hb[1] * y + Hb[2];
    float w1 = Hb[3] * x + Hb[4] * y + Hb[5];
    float w2 = Hb[6] * x + Hb[7] * y + Hb[8];
    float vmc  = (bilinear_ds(vm  + (size_t)b * HH * WW, i, j) > 0.5f) ? 1.f : 0.f;
    float wvmc = (bilinear_ds(wvm + (size_t)b * HH * WW, i, j) > 0.5f) ? 1.f : 0.f;
    g_rowgeo[idx] = make_float4(w1 / w2, w0 / w2, vmc, 0.f);
    g_colgeo[idx] = make_float4(y, x, wvmc, 0.f);
}

// ---------------- main: fp16 mma.sync GEMM, frag-pipelined, KC=64 ----------------
#define TILE 128
#define KC 64
#define KSTR 72                       // halfs/row: 128B data + 16B pad; conflict-free ldmatrix
#define MAT_BYTES (TILE * KSTR * 2)   // 18432
#define STAGE_BYTES (2 * MAT_BYTES)
#define ROW_OFF (2 * STAGE_BYTES)     // 73728
#define COL_OFF (ROW_OFF + TILE * 16)
#define WRED_OFF (COL_OFF + TILE * 16)
#define SMEM_TOTAL (WRED_OFF + 64)
#define NCHUNK (DD / KC)              // 4

__device__ __forceinline__ float lossterm(float acc, float4 r, float4 c) {
    float dot = fmaxf(acc, 0.f);
    float pd = fmaxf(1.0f - dot, 0.f);
    float nd = fmaxf(dot - 0.2f, 0.f);
    float dy = c.x - r.x, dx = c.y - r.y;
    float d2 = dy * dy + dx * dx;
    float w = r.z * c.z;
    return (d2 <= 56.25f) ? 250.f * pd * w : nd * w;   // (CELL-0.5)^2 = 56.25
}

#define LOADFRAG(buf, ksoff)                                                            \
    do {                                                                                \
        _Pragma("unroll")                                                               \
        for (int mt = 0; mt < 4; mt++) {                                                \
            uint32_t addr = abase + (uint32_t)(mt * 16 * KSTR + (ksoff)) * 2;           \
            asm volatile("ldmatrix.sync.aligned.m8n8.x4.shared.b16 {%0,%1,%2,%3}, [%4];"\
                         : "=r"(af[buf][mt][0]), "=r"(af[buf][mt][1]),                  \
                           "=r"(af[buf][mt][2]), "=r"(af[buf][mt][3])                   \
                         : "r"(addr));                                                  \
        }                                                                               \
        _Pragma("unroll")                                                               \
        for (int np = 0; np < 2; np++) {                                                \
            uint32_t addr = bbase + (uint32_t)(np * 16 * KSTR + (ksoff)) * 2;           \
            asm volatile("ldmatrix.sync.aligned.m8n8.x4.shared.b16 {%0,%1,%2,%3}, [%4];"\
                         : "=r"(bf[buf][np][0]), "=r"(bf[buf][np][1]),                  \
                           "=r"(bf[buf][np][2]), "=r"(bf[buf][np][3])                   \
                         : "r"(addr));                                                  \
        }                                                                               \
    } while (0)

#define MMAS(buf)                                                                       \
    do {                                                                                \
        _Pragma("unroll")                                                               \
        for (int np = 0; np < 2; np++)                                                  \
            _Pragma("unroll")                                                           \
            for (int h = 0; h < 2; h++) {                                               \
                int nt = np * 2 + h;                                                    \
                _Pragma("unroll")                                                       \
                for (int mt = 0; mt < 4; mt++) {                                        \
                    asm volatile(                                                       \
                        "mma.sync.aligned.m16n8k16.row.col.f16.f16.f16.f16 "            \
                        "{%0,%1}, {%2,%3,%4,%5}, {%6,%7}, {%0,%1};"                     \
                        : "+r"(acc[mt][nt][0]), "+r"(acc[mt][nt][1])                    \
                        : "r"(af[buf][mt][0]), "r"(af[buf][mt][1]),                     \
                          "r"(af[buf][mt][2]), "r"(af[buf][mt][3]),                     \
                          "r"(bf[buf][np][h * 2]), "r"(bf[buf][np][h * 2 + 1]));        \
                }                                                                       \
            }                                                                           \
    } while (0)

__global__ __launch_bounds__(256, 2) void gemm_loss_kernel() {
    extern __shared__ __align__(16) char dsm[];
    float4* s_row = (float4*)(dsm + ROW_OFF);
    float4* s_col = (float4*)(dsm + COL_OFF);
    float*  wred  = (float*)(dsm + WRED_OFF);

    int b = blockIdx.z;
    int i0 = blockIdx.y * TILE;
    int j0 = blockIdx.x * TILE;
    int tid = threadIdx.x;
    int wid = tid >> 5, lane = tid & 31;

    if (tid < TILE) {
        int r = i0 + tid;
        s_row[tid] = (r < NN) ? g_rowgeo[b * NN + r] : make_float4(0.f, 0.f, 0.f, 0.f);
    } else {
        int t = tid - TILE;
        int c = j0 + t;
        s_col[t] = (c < NN) ? g_colgeo[b * NN + c] : make_float4(0.f, 0.f, 0.f, 0.f);
    }

    const char* A  = (const char*)(g_dnorm  + (size_t)b * NN * DD);
    const char* Bm = (const char*)(g_wdnorm + (size_t)b * NN * DD);

    // cp.async geometry: each chunk row = 128B = 8 x 16B; thread t handles
    // row t>>1, 64B half (t&1) of both A and B (4 segs each).
    int rowT = tid >> 1, colb = (tid & 1) * 64;
    uint32_t okA = (i0 + rowT < NN) ? 16u : 0u;
    uint32_t okB = (j0 + rowT < NN) ? 16u : 0u;
    const char* gA = A  + (size_t)(i0 + rowT) * (DD * 2) + colb;
    const char* gB = Bm + (size_t)(j0 + rowT) * (DD * 2) + colb;
    uint32_t smem0 = smem_u32(dsm);
    uint32_t sA = smem0 + rowT * (KSTR * 2) + colb;
    uint32_t sB = sA + (uint32_t)MAT_BYTES;

    int m_base = (wid >> 2) * 64;     // 0 or 64
    int n_base = (wid & 3) * 32;      // 0,32,64,96
    int g = lane >> 3, lr = lane & 7;

    uint32_t acc[4][4][2];            // fp16x2 accumulators
    #pragma unroll
    for (int i = 0; i < 4; i++)
        #pragma unroll
        for (int j = 0; j < 4; j++) { acc[i][j][0] = 0u; acc[i][j][1] = 0u; }

    uint32_t af[2][4][4], bf[2][2][4];   // double-buffered fragments

    // ldmatrix lane offsets (bytes)
    uint32_t a_row_off = (uint32_t)((m_base + (g & 1) * 8 + lr) * KSTR + (g >> 1) * 8) * 2;
    uint32_t b_row_off = (uint32_t)((n_base + (g >> 1) * 8 + lr) * KSTR + (g & 1) * 8) * 2;

    // prologue: chunk 0 -> stage 0
    #pragma unroll
    for (int q = 0; q < 4; q++) {
        cp_async16(sA + q * 16, gA + q * 16, okA);
        cp_async16(sB + q * 16, gB + q * 16, okB);
    }
    CP_COMMIT();

    #pragma unroll
    for (int ck = 0; ck < NCHUNK; ck++) {
        int s = ck & 1;
        CP_WAIT(0);          // chunk ck's copy complete
        __syncthreads();     // stage s readable; all reads of stage 1-s finished
        if (ck + 1 < NCHUNK) {
            uint32_t so = (uint32_t)((ck + 1) & 1) * STAGE_BYTES;
            int go = (ck + 1) * (KC * 2);
            #pragma unroll
            for (int q = 0; q < 4; q++) {
                cp_async16(sA + so + q * 16, gA + go + q * 16, okA);
                cp_async16(sB + so + q * 16, gB + go + q * 16, okB);
            }
            CP_COMMIT();
        }

        uint32_t abase = smem0 + s * (uint32_t)STAGE_BYTES + a_row_off;
        uint32_t bbase = smem0 + s * (uint32_t)STAGE_BYTES + (uint32_t)MAT_BYTES + b_row_off;

        LOADFRAG(0, 0);                      // preload ks=0 fragments
        #pragma unroll
        for (int ksi = 0; ksi < KC / 16; ksi++) {
            int cur = ksi & 1;
            if (ksi + 1 < KC / 16) LOADFRAG(cur ^ 1, (ksi + 1) * 16);
            MMAS(cur);
        }
    }

    // fused epilogue (unpack half2 accumulators)
    int qr = lane >> 2, qc = (lane & 3) * 2;
    float lsum = 0.f;
    #pragma unroll
    for (int mt = 0; mt < 4; mt++) {
        float4 r0 = s_row[m_base + mt * 16 + qr];
        float4 r1 = s_row[m_base + mt * 16 + qr + 8];
        #pragma unroll
        for (int nt = 0; nt < 4; nt++) {
            float4 c0 = s_col[n_base + nt * 8 + qc];
            float4 c1 = s_col[n_base + nt * 8 + qc + 1];
            float2 d0 = __half22float2(*(__half2*)&acc[mt][nt][0]);
            float2 d1 = __half22float2(*(__half2*)&acc[mt][nt][1]);
            lsum += lossterm(d0.x, r0, c0);
            lsum += lossterm(d0.y, r0, c1);
            lsum += lossterm(d1.x, r1, c0);
            lsum += lossterm(d1.y, r1, c1);
        }
    }

    float v = warpsum(lsum);
    __syncthreads();               // compute done everywhere before wred reuse
    if (lane == 0) wred[wid] = v;
    __syncthreads();
    if (tid == 0) {
        float s = 0;
        #pragma unroll
        for (int u = 0; u < 8; u++) s += wred[u];
        atomicAdd(&g_acc[7], (double)s);
    }
}

// ---------------- finalize (also re-zeros accumulators for next replay) ----------------
__global__ void finalize_kernel(float* __restrict__ out) {
    double np1 = g_acc[2];
    double pl  = (np1 == 0.0) ? -g_acc[1] : -(g_acc[0] + g_acc[1]) / fmax(np1, 1.0);
    double np2 = g_acc[5];
    double wpl = (np2 == 0.0) ? -g_acc[4] : -(g_acc[3] + g_acc[4]) / fmax(np2, 1.0);
    double dl  = g_acc[7] / g_acc[6];
    out[0] = (float)(pl + wpl + 1e-4 * dl);
    out[1] = (float)pl;
    out[2] = (float)wpl;
    out[3] = (float)dl;
    #pragma unroll
    for (int q = 0; q < 8; q++) g_acc[q] = 0.0;
}

// ---------------- launch ----------------
extern "C" void kernel_launch(void* const* d_in, const int* in_sizes, int n_in,
                              void* d_out, int out_size) {
    const float* prob  = (const float*)d_in[0];
    const float* ht    = (const float*)d_in[1];
    const float* vm    = (const float*)d_in[2];
    const float* wprob = (const float*)d_in[3];
    const float* wht   = (const float*)d_in[4];
    const float* wvm   = (const float*)d_in[5];
    const float* desc  = (const float*)d_in[6];
    const float* wdesc = (const float*)d_in[7];
    const float* Hm    = (const float*)d_in[8];
    float* out = (float*)d_out;

    cudaFuncSetAttribute(gemm_loss_kernel,
                         cudaFuncAttributeMaxDynamicSharedMemorySize, SMEM_TOTAL);

    detector_kernel<<<600, 256>>>((const float4*)prob, (const float4*)ht, (const float4*)vm,
                                  (const float4*)wprob, (const float4*)wht, (const float4*)wvm);

    __half* dnorm;  cudaGetSymbolAddress((void**)&dnorm,  g_dnorm);
    __half* wdnorm; cudaGetSymbolAddress((void**)&wdnorm, g_wdnorm);
    normdesc_kernel<<<2 * BB * (NN / 32), 512>>>(desc, dnorm, wdesc, wdnorm);

    coords_kernel<<<(BB * NN + 255) / 256, 256>>>(vm, wvm, Hm);

    dim3 grid((NN + TILE - 1) / TILE, (NN + TILE - 1) / TILE, BB);
    gemm_loss_kernel<<<grid, 256, SMEM_TOTAL>>>();

    finalize_kernel<<<1, 1>>>(out);
}

// round 9
// speedup vs baseline: 1.2238x; 1.1876x over previous
#include <cuda_runtime.h>
#include <cuda_fp16.h>
#include <math.h>
#include <stdint.h>

#define BB 2
#define HH 480
#define WW 640
#define DD 256
#define HC 60
#define WC 80
#define NN 4800          // HC*WC
#define TOTAL_PIX (BB*HH*WW)

// ---------------- device scratch ----------------
// acc: 0 pos1, 1 neg1, 2 npos1, 3 pos2, 4 neg2, 5 npos2, 6 normalization, 7 desc_sum
__device__ double g_acc[8];   // static zero-init; finalize re-zeros after each use
__device__ __align__(16) __half g_dnorm[BB*NN*DD];   // (b, ij, d) fp16 normalized
__device__ __align__(16) __half g_wdnorm[BB*NN*DD];
__device__ float4 g_rowgeo[BB*NN];   // {wy, wx, vm_c, 0}
__device__ float4 g_colgeo[BB*NN];   // {cy, cx, wvm_c, 0}

// ---------------- helpers ----------------
__device__ __forceinline__ float warpsum(float v) {
    #pragma unroll
    for (int o = 16; o; o >>= 1) v += __shfl_down_sync(0xffffffffu, v, o);
    return v;
}

__device__ __forceinline__ uint32_t smem_u32(const void* p) {
    uint32_t a;
    asm("{ .reg .u64 t; cvta.to.shared.u64 t, %1; cvt.u32.u64 %0, t; }" : "=r"(a) : "l"(p));
    return a;
}

__device__ __forceinline__ void cp_async16(uint32_t dst, const void* src, uint32_t bytes) {
    asm volatile("cp.async.cg.shared.global [%0], [%1], 16, %2;"
                 :: "r"(dst), "l"(src), "r"(bytes) : "memory");
}
#define CP_COMMIT() asm volatile("cp.async.commit_group;" ::: "memory")
#define CP_WAIT(n)  asm volatile("cp.async.wait_group %0;" :: "n"(n) : "memory")

// ---------------- detector losses + normalization sum (float4) ----------------
__global__ void detector_kernel(const float4* __restrict__ prob,
                                const float4* __restrict__ ht,
                                const float4* __restrict__ vm,
                                const float4* __restrict__ wprob,
                                const float4* __restrict__ wht,
                                const float4* __restrict__ wvm) {
    float vals[7] = {0, 0, 0, 0, 0, 0, 0};
    const int n4 = TOTAL_PIX / 4;
    for (int i = blockIdx.x * blockDim.x + threadIdx.x; i < n4;
         i += gridDim.x * blockDim.x) {
        float4 p4 = prob[i], h4 = ht[i], v4 = vm[i];
        float4 wp4 = wprob[i], wh4 = wht[i], wv4 = wvm[i];
        #pragma unroll
        for (int q = 0; q < 4; q++) {
            float p = ((const float*)&p4)[q], h = ((const float*)&h4)[q], v = ((const float*)&v4)[q];
            float pi = (h == 1.0f) ? 1.f : 0.f;
            float ni = (h < 1.0f) ? 1.f : 0.f;
            float nw = (1.f - h) * (1.f - h); nw *= nw;
            vals[0] += logf(p + 1e-7f) * (1.f - p) * (1.f - p) * pi * v;
            vals[1] += logf(1.f - p + 1e-7f) * p * p * nw * ni * v;
            vals[2] += pi;
            float wp = ((const float*)&wp4)[q], wh = ((const float*)&wh4)[q], wv = ((const float*)&wv4)[q];
            float wpi = (wh == 1.0f) ? 1.f : 0.f;
            float wni = (wh < 1.0f) ? 1.f : 0.f;
            float wnw = (1.f - wh) * (1.f - wh); wnw *= wnw;
            vals[3] += logf(wp + 1e-7f) * (1.f - wp) * (1.f - wp) * wpi * wv;
            vals[4] += logf(1.f - wp + 1e-7f) * wp * wp * wnw * wni * wv;
            vals[5] += wpi;
            vals[6] += wv;
        }
    }
    __shared__ float w[8];
    int lane = threadIdx.x & 31, warp = threadIdx.x >> 5;
    for (int q = 0; q < 7; q++) {
        float v = warpsum(vals[q]);
        if (lane == 0) w[warp] = v;
        __syncthreads();
        if (threadIdx.x == 0) {
            float s = 0;
            for (int u = 0; u < (int)(blockDim.x >> 5); u++) s += w[u];
            atomicAdd(&g_acc[q], (double)s);
        }
        __syncthreads();
    }
}

// ---------------- descriptor normalize + transpose (fp32 -> fp16), both tensors ----------------
__global__ void normdesc_kernel(const float* __restrict__ src0, __half* __restrict__ dst0,
                                const float* __restrict__ src1, __half* __restrict__ dst1) {
    __shared__ float tile[DD][33];
    __shared__ float part[16][32];
    __shared__ float inv[32];
    int which = blockIdx.x >= BB * (NN / 32);
    int blk = blockIdx.x - which * BB * (NN / 32);
    const float* src = which ? src1 : src0;
    __half* dst = which ? dst1 : dst0;
    int b = blk / (NN / 32);
    int jt = blk % (NN / 32);
    int base = jt * 32;
    const float* s = src + (size_t)b * DD * NN;
    for (int idx = threadIdx.x; idx < DD * 32; idx += 512) {
        int d = idx >> 5, j = idx & 31;
        tile[d][j] = s[d * NN + base + j];
    }
    __syncthreads();
    {
        int j = threadIdx.x & 31, g = threadIdx.x >> 5;
        float acc = 0;
        for (int d = g; d < DD; d += 16) { float v = tile[d][j]; acc += v * v; }
        part[g][j] = acc;
    }
    __syncthreads();
    if (threadIdx.x < 32) {
        float s2 = 0;
        #pragma unroll
        for (int g2 = 0; g2 < 16; g2++) s2 += part[g2][threadIdx.x];
        inv[threadIdx.x] = 1.0f / fmaxf(sqrtf(s2), 1e-12f);
    }
    __syncthreads();
    __half* o = dst + (size_t)b * NN * DD;
    for (int idx = threadIdx.x; idx < 32 * DD; idx += 512) {
        int jj = idx >> 8, d = idx & 255;
        o[(size_t)(base + jj) * DD + d] = __float2half_rn(tile[d][jj] * inv[jj]);
    }
}

// ---------------- warped coords + downsampled masks ----------------
__device__ __forceinline__ float bilinear_ds(const float* __restrict__ img, int i, int j) {
    float sr = (i + 0.5f) * ((float)HH / HC) - 0.5f;
    sr = fminf(fmaxf(sr, 0.f), (float)(HH - 1));
    int r0 = (int)floorf(sr); int r1 = min(r0 + 1, HH - 1); float wr = sr - (float)r0;
    float sc = (j + 0.5f) * ((float)WW / WC) - 0.5f;
    sc = fminf(fmaxf(sc, 0.f), (float)(WW - 1));
    int c0 = (int)floorf(sc); int c1 = min(c0 + 1, WW - 1); float wc = sc - (float)c0;
    float a = img[r0 * WW + c0] * (1.f - wr) + img[r1 * WW + c0] * wr;
    float b = img[r0 * WW + c1] * (1.f - wr) + img[r1 * WW + c1] * wr;
    return a * (1.f - wc) + b * wc;
}

__global__ void coords_kernel(const float* __restrict__ vm,
                              const float* __restrict__ wvm,
                              const float* __restrict__ Hm) {
    int idx = blockIdx.x * blockDim.x + threadIdx.x;
    if (idx >= BB * NN) return;
    int b = idx / NN, ij = idx % NN;
    int i = ij / WC, j = ij % WC;
    float y = (float)(i * 8 + 4), x = (float)(j * 8 + 4);
    const float* Hb = Hm + b * 9;
    float w0 = Hb[0] * x + Hb[1] * y + Hb[2];
    float w1 = Hb[3] * x + Hb[4] * y + Hb[5];
    float w2 = Hb[6] * x + Hb[7] * y + Hb[8];
    float vmc  = (bilinear_ds(vm  + (size_t)b * HH * WW, i, j) > 0.5f) ? 1.f : 0.f;
    float wvmc = (bilinear_ds(wvm + (size_t)b * HH * WW, i, j) > 0.5f) ? 1.f : 0.f;
    g_rowgeo[idx] = make_float4(w1 / w2, w0 / w2, vmc, 0.f);
    g_colgeo[idx] = make_float4(y, x, wvmc, 0.f);
}

// ---------------- main: fp16 mma.sync GEMM, KC=32, 3 CTAs/SM ----------------
#define TILE 128
#define KC 32
#define ASTR 40                       // halfs/row: 64B data + 16B pad; conflict-free ldmatrix
#define ABYTES (TILE * ASTR * 2)      // 10240
#define NCHUNK (DD / KC)              // 8

__device__ __forceinline__ float lossterm(float acc, float4 r, float4 c) {
    float dot = fmaxf(acc, 0.f);
    float pd = fmaxf(1.0f - dot, 0.f);
    float nd = fmaxf(dot - 0.2f, 0.f);
    float dy = c.x - r.x, dx = c.y - r.y;
    float d2 = dy * dy + dx * dx;
    float w = r.z * c.z;
    return (d2 <= 56.25f) ? 250.f * pd * w : nd * w;   // (CELL-0.5)^2 = 56.25
}

__global__ __launch_bounds__(256, 3) void gemm_loss_kernel() {
    __shared__ __align__(16) __half As[2][TILE * ASTR];   // 2 x 10 KB
    __shared__ __align__(16) __half Bs[2][TILE * ASTR];   // 2 x 10 KB
    __shared__ float4 s_row[TILE], s_col[TILE];
    __shared__ float wred[8];

    int b = blockIdx.z;
    int i0 = blockIdx.y * TILE;
    int j0 = blockIdx.x * TILE;
    int tid = threadIdx.x;
    int wid = tid >> 5, lane = tid & 31;

    if (tid < TILE) {
        int r = i0 + tid;
        s_row[tid] = (r < NN) ? g_rowgeo[b * NN + r] : make_float4(0.f, 0.f, 0.f, 0.f);
    } else {
        int t = tid - TILE;
        int c = j0 + t;
        s_col[t] = (c < NN) ? g_colgeo[b * NN + c] : make_float4(0.f, 0.f, 0.f, 0.f);
    }

    const char* A  = (const char*)(g_dnorm  + (size_t)b * NN * DD);
    const char* Bm = (const char*)(g_wdnorm + (size_t)b * NN * DD);

    // cp.async geometry: each chunk row = 64B = 4 x 16B; thread t handles
    // row t>>1, 32B half (t&1) of both A and B (2 segs each).
    int rowT = tid >> 1, colb = (tid & 1) * 32;
    uint32_t okA = (i0 + rowT < NN) ? 16u : 0u;
    uint32_t okB = (j0 + rowT < NN) ? 16u : 0u;
    const char* gA = A  + (size_t)(i0 + rowT) * (DD * 2) + colb;
    const char* gB = Bm + (size_t)(j0 + rowT) * (DD * 2) + colb;
    uint32_t sA = smem_u32(As) + rowT * (ASTR * 2) + colb;
    uint32_t sB = smem_u32(Bs) + rowT * (ASTR * 2) + colb;

    int m_base = (wid >> 2) * 64;     // 0 or 64
    int n_base = (wid & 3) * 32;      // 0,32,64,96
    int g = lane >> 3, lr = lane & 7;

    uint32_t acc[4][4][2];            // fp16x2 accumulators
    #pragma unroll
    for (int i = 0; i < 4; i++)
        #pragma unroll
        for (int j = 0; j < 4; j++) { acc[i][j][0] = 0u; acc[i][j][1] = 0u; }

    uint32_t As_base = smem_u32(As), Bs_base = smem_u32(Bs);
    uint32_t a_row_off = (uint32_t)((m_base + (g & 1) * 8 + lr) * ASTR + (g >> 1) * 8) * 2;
    uint32_t b_row_off = (uint32_t)((n_base + (g >> 1) * 8 + lr) * ASTR + (g & 1) * 8) * 2;

    // prologue: chunk 0 -> stage 0
    cp_async16(sA, gA, okA);      cp_async16(sA + 16, gA + 16, okA);
    cp_async16(sB, gB, okB);      cp_async16(sB + 16, gB + 16, okB);
    CP_COMMIT();

    #pragma unroll
    for (int ck = 0; ck < NCHUNK; ck++) {
        int s = ck & 1;
        CP_WAIT(0);          // chunk ck's copy complete
        __syncthreads();     // stage s readable; all reads of stage 1-s finished
        if (ck + 1 < NCHUNK) {
            uint32_t so = (uint32_t)((ck + 1) & 1) * ABYTES;
            int go = (ck + 1) * (KC * 2);
            cp_async16(sA + so, gA + go, okA);
            cp_async16(sA + so + 16, gA + go + 16, okA);
            cp_async16(sB + so, gB + go, okB);
            cp_async16(sB + so + 16, gB + go + 16, okB);
            CP_COMMIT();
        }

        uint32_t abase = As_base + s * (uint32_t)ABYTES + a_row_off;
        uint32_t bbase = Bs_base + s * (uint32_t)ABYTES + b_row_off;
        #pragma unroll
        for (int ks = 0; ks < KC; ks += 16) {
            uint32_t af[4][4], bf[2][4];
            #pragma unroll
            for (int mt = 0; mt < 4; mt++) {
                uint32_t addr = abase + (uint32_t)(mt * 16 * ASTR + ks) * 2;
                asm volatile("ldmatrix.sync.aligned.m8n8.x4.shared.b16 {%0,%1,%2,%3}, [%4];"
                             : "=r"(af[mt][0]), "=r"(af[mt][1]), "=r"(af[mt][2]), "=r"(af[mt][3])
                             : "r"(addr));
            }
            #pragma unroll
            for (int np = 0; np < 2; np++) {
                uint32_t addr = bbase + (uint32_t)(np * 16 * ASTR + ks) * 2;
                asm volatile("ldmatrix.sync.aligned.m8n8.x4.shared.b16 {%0,%1,%2,%3}, [%4];"
                             : "=r"(bf[np][0]), "=r"(bf[np][1]), "=r"(bf[np][2]), "=r"(bf[np][3])
                             : "r"(addr));
            }
            #pragma unroll
            for (int np = 0; np < 2; np++)
                #pragma unroll
                for (int h = 0; h < 2; h++) {
                    int nt = np * 2 + h;
                    #pragma unroll
                    for (int mt = 0; mt < 4; mt++) {
                        asm volatile(
                            "mma.sync.aligned.m16n8k16.row.col.f16.f16.f16.f16 "
                            "{%0,%1}, {%2,%3,%4,%5}, {%6,%7}, {%0,%1};"
                            : "+r"(acc[mt][nt][0]), "+r"(acc[mt][nt][1])
                            : "r"(af[mt][0]), "r"(af[mt][1]), "r"(af[mt][2]), "r"(af[mt][3]),
                              "r"(bf[np][h * 2]), "r"(bf[np][h * 2 + 1]));
                    }
                }
        }
    }

    // fused epilogue (unpack half2 accumulators)
    int qr = lane >> 2, qc = (lane & 3) * 2;
    float lsum = 0.f;
    #pragma unroll
    for (int mt = 0; mt < 4; mt++) {
        float4 r0 = s_row[m_base + mt * 16 + qr];
        float4 r1 = s_row[m_base + mt * 16 + qr + 8];
        #pragma unroll
        for (int nt = 0; nt < 4; nt++) {
            float4 c0 = s_col[n_base + nt * 8 + qc];
            float4 c1 = s_col[n_base + nt * 8 + qc + 1];
            float2 d0 = __half22float2(*(__half2*)&acc[mt][nt][0]);
            float2 d1 = __half22float2(*(__half2*)&acc[mt][nt][1]);
            lsum += lossterm(d0.x, r0, c0);
            lsum += lossterm(d0.y, r0, c1);
            lsum += lossterm(d1.x, r1, c0);
            lsum += lossterm(d1.y, r1, c1);
        }
    }

    float v = warpsum(lsum);
    if (lane == 0) wred[wid] = v;
    __syncthreads();
    if (tid == 0) {
        float s = 0;
        #pragma unroll
        for (int u = 0; u < 8; u++) s += wred[u];
        atomicAdd(&g_acc[7], (double)s);
    }
}

// ---------------- finalize (also re-zeros accumulators for next replay) ----------------
__global__ void finalize_kernel(float* __restrict__ out) {
    double np1 = g_acc[2];
    double pl  = (np1 == 0.0) ? -g_acc[1] : -(g_acc[0] + g_acc[1]) / fmax(np1, 1.0);
    double np2 = g_acc[5];
    double wpl = (np2 == 0.0) ? -g_acc[4] : -(g_acc[3] + g_acc[4]) / fmax(np2, 1.0);
    double dl  = g_acc[7] / g_acc[6];
    out[0] = (float)(pl + wpl + 1e-4 * dl);
    out[1] = (float)pl;
    out[2] = (float)wpl;
    out[3] = (float)dl;
    #pragma unroll
    for (int q = 0; q < 8; q++) g_acc[q] = 0.0;
}

// ---------------- launch ----------------
extern "C" void kernel_launch(void* const* d_in, const int* in_sizes, int n_in,
                              void* d_out, int out_size) {
    const float* prob  = (const float*)d_in[0];
    const float* ht    = (const float*)d_in[1];
    const float* vm    = (const float*)d_in[2];
    const float* wprob = (const float*)d_in[3];
    const float* wht   = (const float*)d_in[4];
    const float* wvm   = (const float*)d_in[5];
    const float* desc  = (const float*)d_in[6];
    const float* wdesc = (const float*)d_in[7];
    const float* Hm    = (const float*)d_in[8];
    float* out = (float*)d_out;

    detector_kernel<<<600, 256>>>((const float4*)prob, (const float4*)ht, (const float4*)vm,
                                  (const float4*)wprob, (const float4*)wht, (const float4*)wvm);

    __half* dnorm;  cudaGetSymbolAddress((void**)&dnorm,  g_dnorm);
    __half* wdnorm; cudaGetSymbolAddress((void**)&wdnorm, g_wdnorm);
    normdesc_kernel<<<2 * BB * (NN / 32), 512>>>(desc, dnorm, wdesc, wdnorm);

    coords_kernel<<<(BB * NN + 255) / 256, 256>>>(vm, wvm, Hm);

    dim3 grid((NN + TILE - 1) / TILE, (NN + TILE - 1) / TILE, BB);
    gemm_loss_kernel<<<grid, 256>>>();

    finalize_kernel<<<1, 1>>>(out);
}